// round 1
// baseline (speedup 1.0000x reference)
#include <cuda_runtime.h>
#include <cstdint>

#define NB   8
#define CIN  64
#define COUT 128
#define HH   256
#define WW   256
#define HW   65536
#define HEADS 32

// ---- scratch (device globals; no allocation allowed) ----
__device__ float g_a[(size_t)NB * COUT * HW];        // conv+PReLU output (268MB)
__device__ float g_psum[NB * COUT * 128];            // per-block partial sums
__device__ float g_psumsq[NB * COUT * 128];
__device__ float g_mean[NB * COUT];
__device__ float g_inv[NB * COUT];
__device__ float g_kb2[NB * HEADS];
__device__ float g_vb2[NB * HEADS];
__device__ float g_pm[NB * HEADS * 512];             // softmax block partials
__device__ float g_pse[NB * HEADS * 512];
__device__ float g_psev[NB * HEADS * 512];
__device__ float g_ctx[NB * HEADS];
__device__ float g_bias[NB * COUT];

// =====================================================================
// Kernel 1: fused (x-y)+x*y  ->  3x3 conv (64->128) -> +bias -> PReLU
//           -> write g_a, deterministic per-block sum/sumsq partials
// Tile: 32(w) x 16(h) spatial, 16 out channels. 256 threads.
// Thread: 4 spatial rows x 8 out channels (32 accumulators).
// =====================================================================
__global__ __launch_bounds__(256) void conv_kernel(
    const float* __restrict__ x, const float* __restrict__ y,
    const float* __restrict__ cw, const float* __restrict__ cb,
    const float* __restrict__ pa_ptr)
{
    __shared__ float s_in[8][18][34];    // ci-chunk x (16+2) x (32+2)
    __shared__ float s_w[16][8][9];      // cout x ci-chunk x tap
    __shared__ float s_ps[8][8], s_pss[8][8];

    const int bx = blockIdx.x, by = blockIdx.y;
    const int nz = blockIdx.z;
    const int n = nz >> 3;               // batch
    const int cog = nz & 7;              // cout group (16 ch each)
    const int gx0 = bx * 32, gy0 = by * 16;
    const int tx = threadIdx.x;

    float acc[4][8];
#pragma unroll
    for (int dy = 0; dy < 4; dy++)
#pragma unroll
        for (int j = 0; j < 8; j++) acc[dy][j] = 0.f;

    const float* xb = x + (size_t)n * CIN * HW;
    const float* yb = y + (size_t)n * CIN * HW;

    const int co_sub = tx >> 7;          // 0/1
    const int sp = tx & 127;
    const int lx = sp & 31;
    const int ly0 = (sp >> 5) << 2;      // 0,4,8,12

    for (int cc = 0; cc < 8; cc++) {
        // load input tile (compute mixed on the fly, zero-pad borders)
        for (int e = tx; e < 8 * 18 * 34; e += 256) {
            int lci = e / 612;
            int r = e - lci * 612;
            int ly = r / 34;
            int lxx = r - ly * 34;
            int gy = gy0 + ly - 1, gx = gx0 + lxx - 1;
            float v = 0.f;
            if ((unsigned)gy < 256u && (unsigned)gx < 256u) {
                size_t gi = (size_t)(cc * 8 + lci) * HW + gy * 256 + gx;
                float xv = __ldg(xb + gi), yv = __ldg(yb + gi);
                v = (xv - yv) + xv * yv;
            }
            s_in[lci][ly][lxx] = v;
        }
        // load weights for this (cout group, ci chunk)
        for (int e = tx; e < 16 * 72; e += 256) {
            int co = e / 72;
            int r = e - co * 72;     // ci*9 + k
            ((float*)s_w)[co * 72 + r] =
                __ldg(cw + (size_t)(cog * 16 + co) * (CIN * 9) + cc * 72 + r);
        }
        __syncthreads();

#pragma unroll
        for (int ci = 0; ci < 8; ci++) {
            float iv[6][3];
#pragma unroll
            for (int r = 0; r < 6; r++)
#pragma unroll
                for (int c = 0; c < 3; c++)
                    iv[r][c] = s_in[ci][ly0 + r][lx + c];
#pragma unroll
            for (int ky = 0; ky < 3; ky++)
#pragma unroll
                for (int kx = 0; kx < 3; kx++) {
                    float wv[8];
#pragma unroll
                    for (int j = 0; j < 8; j++)
                        wv[j] = s_w[co_sub * 8 + j][ci][ky * 3 + kx];
#pragma unroll
                    for (int dy = 0; dy < 4; dy++) {
                        float ivv = iv[ky + dy][kx];
#pragma unroll
                        for (int j = 0; j < 8; j++)
                            acc[dy][j] = fmaf(ivv, wv[j], acc[dy][j]);
                    }
                }
        }
        __syncthreads();
    }

    // epilogue: +bias, PReLU, store, stats partials
    const float pa = __ldg(pa_ptr);
    const int co0 = cog * 16 + co_sub * 8;
    float ps[8], pss[8];
#pragma unroll
    for (int j = 0; j < 8; j++) { ps[j] = 0.f; pss[j] = 0.f; }

#pragma unroll
    for (int j = 0; j < 8; j++) {
        float b = __ldg(cb + co0 + j);
#pragma unroll
        for (int dy = 0; dy < 4; dy++) {
            float v = acc[dy][j] + b;
            v = (v >= 0.f) ? v : pa * v;
            ps[j] += v;
            pss[j] += v * v;
            int gy = gy0 + ly0 + dy, gx = gx0 + lx;
            g_a[(size_t)(n * COUT + co0 + j) * HW + gy * 256 + gx] = v;
        }
    }

    const int lane = tx & 31, wrp = tx >> 5;
#pragma unroll
    for (int j = 0; j < 8; j++) {
#pragma unroll
        for (int o = 16; o; o >>= 1) {
            ps[j]  += __shfl_down_sync(0xffffffffu, ps[j],  o);
            pss[j] += __shfl_down_sync(0xffffffffu, pss[j], o);
        }
    }
    if (lane == 0) {
#pragma unroll
        for (int j = 0; j < 8; j++) { s_ps[wrp][j] = ps[j]; s_pss[wrp][j] = pss[j]; }
    }
    __syncthreads();
    if (tx < 16) {
        int cs = tx >> 3, j = tx & 7;
        float S = 0.f, SS = 0.f;
#pragma unroll
        for (int ww = 0; ww < 4; ww++) { S += s_ps[cs * 4 + ww][j]; SS += s_pss[cs * 4 + ww][j]; }
        int co = cog * 16 + cs * 8 + j;
        int sb = by * 8 + bx;  // 0..127 deterministic slot
        g_psum[(n * COUT + co) * 128 + sb] = S;
        g_psumsq[(n * COUT + co) * 128 + sb] = SS;
    }
}

// =====================================================================
// Kernel 2: finalize mean / inv_std per (n,c)  (1024 blocks x 128 thr)
// =====================================================================
__global__ void stats_kernel()
{
    const int nc = blockIdx.x;
    const int t = threadIdx.x;
    float S = g_psum[nc * 128 + t];
    float SS = g_psumsq[nc * 128 + t];
#pragma unroll
    for (int o = 16; o; o >>= 1) {
        S += __shfl_down_sync(0xffffffffu, S, o);
        SS += __shfl_down_sync(0xffffffffu, SS, o);
    }
    __shared__ float sS[4], sSS[4];
    if ((t & 31) == 0) { sS[t >> 5] = S; sSS[t >> 5] = SS; }
    __syncthreads();
    if (t == 0) {
        S = sS[0] + sS[1] + sS[2] + sS[3];
        SS = sSS[0] + sSS[1] + sSS[2] + sSS[3];
        float mean = S * (1.f / 65536.f);
        float var = SS * (1.f / 65536.f) - mean * mean;
        g_mean[nc] = mean;
        g_inv[nc] = rsqrtf(var + 1e-5f);
    }
}

// =====================================================================
// Kernel 2b: effective projection biases (norm folded):
//   kb2[n,h] = kb[h] - sum_c kw[h,c]*mean[n,c]*inv[n,c]
// =====================================================================
__global__ void kb2_kernel(const float* __restrict__ kw, const float* __restrict__ kb,
                           const float* __restrict__ vw, const float* __restrict__ vb)
{
    int t = threadIdx.x;           // 256 = 8n x 32h
    int n = t >> 5, h = t & 31;
    float k2 = __ldg(kb + h), v2 = __ldg(vb + h);
    for (int c = 0; c < 128; c++) {
        float mi = g_mean[n * 128 + c] * g_inv[n * 128 + c];
        k2 -= __ldg(kw + h * 128 + c) * mi;
        v2 -= __ldg(vw + h * 128 + c) * mi;
    }
    g_kb2[t] = k2;
    g_vb2[t] = v2;
}

// =====================================================================
// Kernel 3: keys/values projection (norm folded into weights) + per-block
//           online-softmax partials (max, sum-exp, sum-exp*v) per head.
// grid (512 spatial chunks, 8 batch), 128 threads, each thread 1 spatial pos.
// =====================================================================
__global__ __launch_bounds__(128) void proj_kernel(
    const float* __restrict__ kw, const float* __restrict__ vw)
{
    __shared__ float s_buf[8192];   // phase A: kw2|vw2 ; phase B: k|v
    float* s_kw2 = s_buf;
    float* s_vw2 = s_buf + 4096;

    const int n = blockIdx.y;
    const int tx = threadIdx.x;

    for (int e = tx; e < 4096; e += 128) {
        float iv = g_inv[n * 128 + (e & 127)];
        s_kw2[e] = __ldg(kw + e) * iv;
        s_vw2[e] = __ldg(vw + e) * iv;
    }
    __syncthreads();

    const int s = blockIdx.x * 128 + tx;
    const float* p = g_a + (size_t)n * COUT * HW + s;

    float kk[32], vv[32];
#pragma unroll
    for (int h = 0; h < 32; h++) { kk[h] = 0.f; vv[h] = 0.f; }

#pragma unroll 4
    for (int c = 0; c < 128; c++) {
        float av = p[(size_t)c * HW];
#pragma unroll
        for (int h = 0; h < 32; h++) {
            kk[h] = fmaf(av, s_kw2[h * 128 + c], kk[h]);
            vv[h] = fmaf(av, s_vw2[h * 128 + c], vv[h]);
        }
    }
#pragma unroll
    for (int h = 0; h < 32; h++) {
        kk[h] += g_kb2[n * 32 + h];
        vv[h] += g_vb2[n * 32 + h];
    }
    __syncthreads();   // done reading kw2/vw2

    float* s_k = s_buf;
    float* s_v = s_buf + 4096;
#pragma unroll
    for (int h = 0; h < 32; h++) { s_k[h * 128 + tx] = kk[h]; s_v[h * 128 + tx] = vv[h]; }
    __syncthreads();

    const int lane = tx & 31, wrp = tx >> 5;
    for (int j = 0; j < 8; j++) {
        int h = wrp * 8 + j;
        float a0 = s_k[h * 128 + lane];
        float a1 = s_k[h * 128 + lane + 32];
        float a2 = s_k[h * 128 + lane + 64];
        float a3 = s_k[h * 128 + lane + 96];
        float m = fmaxf(fmaxf(a0, a1), fmaxf(a2, a3));
#pragma unroll
        for (int o = 16; o; o >>= 1) m = fmaxf(m, __shfl_xor_sync(0xffffffffu, m, o));
        float e0 = expf(a0 - m), e1 = expf(a1 - m), e2 = expf(a2 - m), e3 = expf(a3 - m);
        float se = e0 + e1 + e2 + e3;
        float sev = e0 * s_v[h * 128 + lane]      + e1 * s_v[h * 128 + lane + 32]
                  + e2 * s_v[h * 128 + lane + 64] + e3 * s_v[h * 128 + lane + 96];
#pragma unroll
        for (int o = 16; o; o >>= 1) {
            se += __shfl_xor_sync(0xffffffffu, se, o);
            sev += __shfl_xor_sync(0xffffffffu, sev, o);
        }
        if (lane == 0) {
            int idx = (n * 32 + h) * 512 + blockIdx.x;
            g_pm[idx] = m;
            g_pse[idx] = se;
            g_psev[idx] = sev;
        }
    }
}

// =====================================================================
// Kernel 4: merge softmax partials -> context[n,h]
// =====================================================================
__global__ void ctx_kernel()
{
    const int nh = blockIdx.x;
    const int t = threadIdx.x;      // 128
    const int base = nh * 512;
    const int lane = t & 31, wrp = t >> 5;
    __shared__ float sred[4];
    __shared__ float sM;

    float lm[4];
    float m = -1e30f;
#pragma unroll
    for (int i = 0; i < 4; i++) {
        lm[i] = g_pm[base + t + 128 * i];
        m = fmaxf(m, lm[i]);
    }
#pragma unroll
    for (int o = 16; o; o >>= 1) m = fmaxf(m, __shfl_xor_sync(0xffffffffu, m, o));
    if (lane == 0) sred[wrp] = m;
    __syncthreads();
    if (t == 0) sM = fmaxf(fmaxf(sred[0], sred[1]), fmaxf(sred[2], sred[3]));
    __syncthreads();
    const float M = sM;

    float S = 0.f, SV = 0.f;
#pragma unroll
    for (int i = 0; i < 4; i++) {
        int idx = base + t + 128 * i;
        float sc = expf(lm[i] - M);
        S += g_pse[idx] * sc;
        SV += g_psev[idx] * sc;
    }
#pragma unroll
    for (int o = 16; o; o >>= 1) {
        S += __shfl_xor_sync(0xffffffffu, S, o);
        SV += __shfl_xor_sync(0xffffffffu, SV, o);
    }
    __shared__ float sS[4], sSV[4];
    if (lane == 0) { sS[wrp] = S; sSV[wrp] = SV; }
    __syncthreads();
    if (t == 0) {
        S = sS[0] + sS[1] + sS[2] + sS[3];
        SV = sSV[0] + sSV[1] + sSV[2] + sSV[3];
        g_ctx[nh] = SV / S;
    }
}

// =====================================================================
// Kernel 5: bias[n,c] = reproj_b[c] + sum_h reproj_w[c,h] * ctx[n,h]
// =====================================================================
__global__ void biasout_kernel(const float* __restrict__ rw, const float* __restrict__ rb)
{
    int n = blockIdx.x;
    int c = threadIdx.x;   // 128
    float b = __ldg(rb + c);
#pragma unroll
    for (int h = 0; h < 32; h++)
        b += __ldg(rw + c * 32 + h) * g_ctx[n * 32 + h];
    g_bias[n * 128 + c] = b;
}

// =====================================================================
// Kernel 6: out = (a - mean)*inv + bias   (vectorized float4)
// =====================================================================
__global__ void out_kernel(float* __restrict__ out)
{
    size_t i4 = (size_t)blockIdx.x * 256 + threadIdx.x;   // 16777216 total
    int nc = (int)(i4 >> 14);                              // (i4*4) >> 16
    float inv = g_inv[nc];
    float off = g_bias[nc] - g_mean[nc] * inv;
    float4 v = ((const float4*)g_a)[i4];
    v.x = fmaf(v.x, inv, off);
    v.y = fmaf(v.y, inv, off);
    v.z = fmaf(v.z, inv, off);
    v.w = fmaf(v.w, inv, off);
    ((float4*)out)[i4] = v;
}

extern "C" void kernel_launch(void* const* d_in, const int* in_sizes, int n_in,
                              void* d_out, int out_size)
{
    const float* x  = (const float*)d_in[0];
    const float* y  = (const float*)d_in[1];
    const float* cw = (const float*)d_in[2];
    const float* cb = (const float*)d_in[3];
    const float* pa = (const float*)d_in[4];
    const float* kw = (const float*)d_in[5];
    const float* kb = (const float*)d_in[6];
    // d_in[7], d_in[8] = queries_w/b: mathematically dead (softmax over size-1 axis)
    const float* vw = (const float*)d_in[9];
    const float* vb = (const float*)d_in[10];
    const float* rw = (const float*)d_in[11];
    const float* rb = (const float*)d_in[12];

    dim3 cgrid(8, 16, 64);
    conv_kernel<<<cgrid, 256>>>(x, y, cw, cb, pa);
    stats_kernel<<<1024, 128>>>();
    kb2_kernel<<<1, 256>>>(kw, kb, vw, vb);
    proj_kernel<<<dim3(512, 8), 128>>>(kw, vw);
    ctx_kernel<<<256, 128>>>();
    biasout_kernel<<<8, 128>>>(rw, rb);
    out_kernel<<<65536, 256>>>((float*)d_out);
}

// round 2
// speedup vs baseline: 1.0013x; 1.0013x over previous
#include <cuda_runtime.h>
#include <cstdint>

#define NB   8
#define CIN  64
#define COUT 128
#define HH   256
#define WW   256
#define HW   65536
#define HEADS 32

// ---- scratch (device globals; no allocation allowed) ----
__device__ float g_a[(size_t)NB * COUT * HW];        // conv+PReLU output (268MB)
__device__ float g_psum[NB * COUT * 128];            // per-block partial sums
__device__ float g_psumsq[NB * COUT * 128];
__device__ float g_mean[NB * COUT];
__device__ float g_inv[NB * COUT];
__device__ float g_kb2[NB * HEADS];
__device__ float g_vb2[NB * HEADS];
__device__ float g_pm[NB * HEADS * 512];             // softmax block partials
__device__ float g_pse[NB * HEADS * 512];
__device__ float g_psev[NB * HEADS * 512];
__device__ float g_ctx[NB * HEADS];
__device__ float g_bias[NB * COUT];

// =====================================================================
// Kernel 1: fused (x-y)+x*y  ->  3x3 conv (64->128) -> +bias -> PReLU
//           -> write g_a, deterministic per-block sum/sumsq partials
// Tile: 32(w) x 16(h) spatial, 16 out channels. 256 threads.
// Thread: 4 spatial rows x 8 out channels (32 accumulators).
// =====================================================================
__global__ __launch_bounds__(256) void conv_kernel(
    const float* __restrict__ x, const float* __restrict__ y,
    const float* __restrict__ cw, const float* __restrict__ cb,
    const float* __restrict__ pa_ptr)
{
    __shared__ float s_in[8][18][34];    // ci-chunk x (16+2) x (32+2)
    __shared__ float s_w[16][8][9];      // cout x ci-chunk x tap
    __shared__ float s_ps[8][8], s_pss[8][8];

    const int bx = blockIdx.x, by = blockIdx.y;
    const int nz = blockIdx.z;
    const int n = nz >> 3;               // batch
    const int cog = nz & 7;              // cout group (16 ch each)
    const int gx0 = bx * 32, gy0 = by * 16;
    const int tx = threadIdx.x;

    float acc[4][8];
#pragma unroll
    for (int dy = 0; dy < 4; dy++)
#pragma unroll
        for (int j = 0; j < 8; j++) acc[dy][j] = 0.f;

    const float* xb = x + (size_t)n * CIN * HW;
    const float* yb = y + (size_t)n * CIN * HW;

    const int co_sub = tx >> 7;          // 0/1
    const int sp = tx & 127;
    const int lx = sp & 31;
    const int ly0 = (sp >> 5) << 2;      // 0,4,8,12

    for (int cc = 0; cc < 8; cc++) {
        // load input tile (compute mixed on the fly, zero-pad borders)
        for (int e = tx; e < 8 * 18 * 34; e += 256) {
            int lci = e / 612;
            int r = e - lci * 612;
            int ly = r / 34;
            int lxx = r - ly * 34;
            int gy = gy0 + ly - 1, gx = gx0 + lxx - 1;
            float v = 0.f;
            if ((unsigned)gy < 256u && (unsigned)gx < 256u) {
                size_t gi = (size_t)(cc * 8 + lci) * HW + gy * 256 + gx;
                float xv = __ldg(xb + gi), yv = __ldg(yb + gi);
                v = (xv - yv) + xv * yv;
            }
            s_in[lci][ly][lxx] = v;
        }
        // load weights for this (cout group, ci chunk)
        for (int e = tx; e < 16 * 72; e += 256) {
            int co = e / 72;
            int r = e - co * 72;     // ci*9 + k
            ((float*)s_w)[co * 72 + r] =
                __ldg(cw + (size_t)(cog * 16 + co) * (CIN * 9) + cc * 72 + r);
        }
        __syncthreads();

#pragma unroll
        for (int ci = 0; ci < 8; ci++) {
            float iv[6][3];
#pragma unroll
            for (int r = 0; r < 6; r++)
#pragma unroll
                for (int c = 0; c < 3; c++)
                    iv[r][c] = s_in[ci][ly0 + r][lx + c];
#pragma unroll
            for (int ky = 0; ky < 3; ky++)
#pragma unroll
                for (int kx = 0; kx < 3; kx++) {
                    float wv[8];
#pragma unroll
                    for (int j = 0; j < 8; j++)
                        wv[j] = s_w[co_sub * 8 + j][ci][ky * 3 + kx];
#pragma unroll
                    for (int dy = 0; dy < 4; dy++) {
                        float ivv = iv[ky + dy][kx];
#pragma unroll
                        for (int j = 0; j < 8; j++)
                            acc[dy][j] = fmaf(ivv, wv[j], acc[dy][j]);
                    }
                }
        }
        __syncthreads();
    }

    // epilogue: +bias, PReLU, store, stats partials
    const float pa = __ldg(pa_ptr);
    const int co0 = cog * 16 + co_sub * 8;
    float ps[8], pss[8];
#pragma unroll
    for (int j = 0; j < 8; j++) { ps[j] = 0.f; pss[j] = 0.f; }

#pragma unroll
    for (int j = 0; j < 8; j++) {
        float b = __ldg(cb + co0 + j);
#pragma unroll
        for (int dy = 0; dy < 4; dy++) {
            float v = acc[dy][j] + b;
            v = (v >= 0.f) ? v : pa * v;
            ps[j] += v;
            pss[j] += v * v;
            int gy = gy0 + ly0 + dy, gx = gx0 + lx;
            g_a[(size_t)(n * COUT + co0 + j) * HW + gy * 256 + gx] = v;
        }
    }

    const int lane = tx & 31, wrp = tx >> 5;
#pragma unroll
    for (int j = 0; j < 8; j++) {
#pragma unroll
        for (int o = 16; o; o >>= 1) {
            ps[j]  += __shfl_down_sync(0xffffffffu, ps[j],  o);
            pss[j] += __shfl_down_sync(0xffffffffu, pss[j], o);
        }
    }
    if (lane == 0) {
#pragma unroll
        for (int j = 0; j < 8; j++) { s_ps[wrp][j] = ps[j]; s_pss[wrp][j] = pss[j]; }
    }
    __syncthreads();
    if (tx < 16) {
        int cs = tx >> 3, j = tx & 7;
        float S = 0.f, SS = 0.f;
#pragma unroll
        for (int ww = 0; ww < 4; ww++) { S += s_ps[cs * 4 + ww][j]; SS += s_pss[cs * 4 + ww][j]; }
        int co = cog * 16 + cs * 8 + j;
        int sb = by * 8 + bx;  // 0..127 deterministic slot
        g_psum[(n * COUT + co) * 128 + sb] = S;
        g_psumsq[(n * COUT + co) * 128 + sb] = SS;
    }
}

// =====================================================================
// Kernel 2: finalize mean / inv_std per (n,c)  (1024 blocks x 128 thr)
// =====================================================================
__global__ void stats_kernel()
{
    const int nc = blockIdx.x;
    const int t = threadIdx.x;
    float S = g_psum[nc * 128 + t];
    float SS = g_psumsq[nc * 128 + t];
#pragma unroll
    for (int o = 16; o; o >>= 1) {
        S += __shfl_down_sync(0xffffffffu, S, o);
        SS += __shfl_down_sync(0xffffffffu, SS, o);
    }
    __shared__ float sS[4], sSS[4];
    if ((t & 31) == 0) { sS[t >> 5] = S; sSS[t >> 5] = SS; }
    __syncthreads();
    if (t == 0) {
        S = sS[0] + sS[1] + sS[2] + sS[3];
        SS = sSS[0] + sSS[1] + sSS[2] + sSS[3];
        float mean = S * (1.f / 65536.f);
        float var = SS * (1.f / 65536.f) - mean * mean;
        g_mean[nc] = mean;
        g_inv[nc] = rsqrtf(var + 1e-5f);
    }
}

// =====================================================================
// Kernel 2b: effective projection biases (norm folded):
//   kb2[n,h] = kb[h] - sum_c kw[h,c]*mean[n,c]*inv[n,c]
// =====================================================================
__global__ void kb2_kernel(const float* __restrict__ kw, const float* __restrict__ kb,
                           const float* __restrict__ vw, const float* __restrict__ vb)
{
    int t = threadIdx.x;           // 256 = 8n x 32h
    int n = t >> 5, h = t & 31;
    float k2 = __ldg(kb + h), v2 = __ldg(vb + h);
    for (int c = 0; c < 128; c++) {
        float mi = g_mean[n * 128 + c] * g_inv[n * 128 + c];
        k2 -= __ldg(kw + h * 128 + c) * mi;
        v2 -= __ldg(vw + h * 128 + c) * mi;
    }
    g_kb2[t] = k2;
    g_vb2[t] = v2;
}

// =====================================================================
// Kernel 3: keys/values projection (norm folded into weights) + per-block
//           online-softmax partials (max, sum-exp, sum-exp*v) per head.
// grid (512 spatial chunks, 8 batch), 128 threads, each thread 1 spatial pos.
// =====================================================================
__global__ __launch_bounds__(128) void proj_kernel(
    const float* __restrict__ kw, const float* __restrict__ vw)
{
    __shared__ float s_buf[8192];   // phase A: kw2|vw2 ; phase B: k|v
    float* s_kw2 = s_buf;
    float* s_vw2 = s_buf + 4096;

    const int n = blockIdx.y;
    const int tx = threadIdx.x;

    for (int e = tx; e < 4096; e += 128) {
        float iv = g_inv[n * 128 + (e & 127)];
        s_kw2[e] = __ldg(kw + e) * iv;
        s_vw2[e] = __ldg(vw + e) * iv;
    }
    __syncthreads();

    const int s = blockIdx.x * 128 + tx;
    const float* p = g_a + (size_t)n * COUT * HW + s;

    float kk[32], vv[32];
#pragma unroll
    for (int h = 0; h < 32; h++) { kk[h] = 0.f; vv[h] = 0.f; }

#pragma unroll 4
    for (int c = 0; c < 128; c++) {
        float av = p[(size_t)c * HW];
#pragma unroll
        for (int h = 0; h < 32; h++) {
            kk[h] = fmaf(av, s_kw2[h * 128 + c], kk[h]);
            vv[h] = fmaf(av, s_vw2[h * 128 + c], vv[h]);
        }
    }
#pragma unroll
    for (int h = 0; h < 32; h++) {
        kk[h] += g_kb2[n * 32 + h];
        vv[h] += g_vb2[n * 32 + h];
    }
    __syncthreads();   // done reading kw2/vw2

    float* s_k = s_buf;
    float* s_v = s_buf + 4096;
#pragma unroll
    for (int h = 0; h < 32; h++) { s_k[h * 128 + tx] = kk[h]; s_v[h * 128 + tx] = vv[h]; }
    __syncthreads();

    const int lane = tx & 31, wrp = tx >> 5;
    for (int j = 0; j < 8; j++) {
        int h = wrp * 8 + j;
        float a0 = s_k[h * 128 + lane];
        float a1 = s_k[h * 128 + lane + 32];
        float a2 = s_k[h * 128 + lane + 64];
        float a3 = s_k[h * 128 + lane + 96];
        float m = fmaxf(fmaxf(a0, a1), fmaxf(a2, a3));
#pragma unroll
        for (int o = 16; o; o >>= 1) m = fmaxf(m, __shfl_xor_sync(0xffffffffu, m, o));
        float e0 = expf(a0 - m), e1 = expf(a1 - m), e2 = expf(a2 - m), e3 = expf(a3 - m);
        float se = e0 + e1 + e2 + e3;
        float sev = e0 * s_v[h * 128 + lane]      + e1 * s_v[h * 128 + lane + 32]
                  + e2 * s_v[h * 128 + lane + 64] + e3 * s_v[h * 128 + lane + 96];
#pragma unroll
        for (int o = 16; o; o >>= 1) {
            se += __shfl_xor_sync(0xffffffffu, se, o);
            sev += __shfl_xor_sync(0xffffffffu, sev, o);
        }
        if (lane == 0) {
            int idx = (n * 32 + h) * 512 + blockIdx.x;
            g_pm[idx] = m;
            g_pse[idx] = se;
            g_psev[idx] = sev;
        }
    }
}

// =====================================================================
// Kernel 4: merge softmax partials -> context[n,h]
// =====================================================================
__global__ void ctx_kernel()
{
    const int nh = blockIdx.x;
    const int t = threadIdx.x;      // 128
    const int base = nh * 512;
    const int lane = t & 31, wrp = t >> 5;
    __shared__ float sred[4];
    __shared__ float sM;

    float lm[4];
    float m = -1e30f;
#pragma unroll
    for (int i = 0; i < 4; i++) {
        lm[i] = g_pm[base + t + 128 * i];
        m = fmaxf(m, lm[i]);
    }
#pragma unroll
    for (int o = 16; o; o >>= 1) m = fmaxf(m, __shfl_xor_sync(0xffffffffu, m, o));
    if (lane == 0) sred[wrp] = m;
    __syncthreads();
    if (t == 0) sM = fmaxf(fmaxf(sred[0], sred[1]), fmaxf(sred[2], sred[3]));
    __syncthreads();
    const float M = sM;

    float S = 0.f, SV = 0.f;
#pragma unroll
    for (int i = 0; i < 4; i++) {
        int idx = base + t + 128 * i;
        float sc = expf(lm[i] - M);
        S += g_pse[idx] * sc;
        SV += g_psev[idx] * sc;
    }
#pragma unroll
    for (int o = 16; o; o >>= 1) {
        S += __shfl_xor_sync(0xffffffffu, S, o);
        SV += __shfl_xor_sync(0xffffffffu, SV, o);
    }
    __shared__ float sS[4], sSV[4];
    if (lane == 0) { sS[wrp] = S; sSV[wrp] = SV; }
    __syncthreads();
    if (t == 0) {
        S = sS[0] + sS[1] + sS[2] + sS[3];
        SV = sSV[0] + sSV[1] + sSV[2] + sSV[3];
        g_ctx[nh] = SV / S;
    }
}

// =====================================================================
// Kernel 5: bias[n,c] = reproj_b[c] + sum_h reproj_w[c,h] * ctx[n,h]
// =====================================================================
__global__ void biasout_kernel(const float* __restrict__ rw, const float* __restrict__ rb)
{
    int n = blockIdx.x;
    int c = threadIdx.x;   // 128
    float b = __ldg(rb + c);
#pragma unroll
    for (int h = 0; h < 32; h++)
        b += __ldg(rw + c * 32 + h) * g_ctx[n * 32 + h];
    g_bias[n * 128 + c] = b;
}

// =====================================================================
// Kernel 6: out = (a - mean)*inv + bias   (vectorized float4)
// =====================================================================
__global__ void out_kernel(float* __restrict__ out)
{
    size_t i4 = (size_t)blockIdx.x * 256 + threadIdx.x;   // 16777216 total
    int nc = (int)(i4 >> 14);                              // (i4*4) >> 16
    float inv = g_inv[nc];
    float off = g_bias[nc] - g_mean[nc] * inv;
    float4 v = ((const float4*)g_a)[i4];
    v.x = fmaf(v.x, inv, off);
    v.y = fmaf(v.y, inv, off);
    v.z = fmaf(v.z, inv, off);
    v.w = fmaf(v.w, inv, off);
    ((float4*)out)[i4] = v;
}

extern "C" void kernel_launch(void* const* d_in, const int* in_sizes, int n_in,
                              void* d_out, int out_size)
{
    const float* x  = (const float*)d_in[0];
    const float* y  = (const float*)d_in[1];
    const float* cw = (const float*)d_in[2];
    const float* cb = (const float*)d_in[3];
    const float* pa = (const float*)d_in[4];
    const float* kw = (const float*)d_in[5];
    const float* kb = (const float*)d_in[6];
    // d_in[7], d_in[8] = queries_w/b: mathematically dead (softmax over size-1 axis)
    const float* vw = (const float*)d_in[9];
    const float* vb = (const float*)d_in[10];
    const float* rw = (const float*)d_in[11];
    const float* rb = (const float*)d_in[12];

    dim3 cgrid(8, 16, 64);
    conv_kernel<<<cgrid, 256>>>(x, y, cw, cb, pa);
    stats_kernel<<<1024, 128>>>();
    kb2_kernel<<<1, 256>>>(kw, kb, vw, vb);
    proj_kernel<<<dim3(512, 8), 128>>>(kw, vw);
    ctx_kernel<<<256, 128>>>();
    biasout_kernel<<<8, 128>>>(rw, rb);
    out_kernel<<<65536, 256>>>((float*)d_out);
}